// round 15
// baseline (speedup 1.0000x reference)
#include <cuda_runtime.h>
#include <cuda_bf16.h>
#include <cstdint>

// CLUB loss, single-pass formulation.
//   result = ( -0.5*P + 0.5/N * sum_d [ X2_d*S_d - 2*X_d*T_d ] ) / N
// with  P    = sum_{i,d} (x^2 - 2*x*mu) * exp(-lv)
//       X_d  = sum_i x,   X2_d = sum_i x^2
//       S_d  = sum_i exp(-lv),   T_d = sum_i mu*exp(-lv)
// (The mu^2 terms cancel between positive and negative.)
//
// Shapes: x (16,512,32,32) f32, p_mu (16384,512) f32, p_logvar (16384,512) f32.
//
// Single fused kernel: pipelined cp.async streaming (R13 main, frozen) +
// atomicAdd per-d combine + last-block ticket finalize (12 KB L2-resident
// combine, done in double). No second launch.

#define DD   512
#define HW   1024
#define NTOK 16384

// Per-launch accumulators. Zero at load; the last block re-zeroes after
// consuming, so the zero-at-entry invariant holds across graph replays.
__device__ float        gAcc[4 * DD];   // [a][d] atomic accumulation targets
__device__ float        gP[1024];       // per-block scalar partials (overwritten)
__device__ unsigned int gTicket;        // reset to 0 by last block each launch

__device__ __forceinline__ void cp16(unsigned int dst, const float* src) {
    asm volatile("cp.async.cg.shared.global [%0], [%1], 16;" :: "r"(dst), "l"(src));
}

// x tile: [feature][16 tokens], pitch 16 floats, XOR chunk swizzle
// c' = c ^ ((f>>1)&3) -> conflict-free LDS.128 on store and load sides.
__device__ __forceinline__ int xword(int f, int c) {
    return (f << 4) + ((c ^ ((f >> 1) & 3)) << 2);
}

// Grid: 1024 blocks = 8 feature-chunks (64 each) x 128 token-slices (128 each).
__global__ __launch_bounds__(256) void club_main_kernel(
    const float* __restrict__ x,
    const float* __restrict__ pmu,
    const float* __restrict__ plv,
    float* __restrict__ out)
{
    __shared__ float xs[2][64 * 16];    // 2 x 4 KB
    __shared__ float mus[2][16 * 64];   // 2 x 4 KB
    __shared__ float lvs[2][16 * 64];   // 2 x 4 KB
    __shared__ float red[4 * 4 * 64];   // [acc][tseg][feature]
    __shared__ float spc[8];
    __shared__ bool  amLast;

    const int tid = threadIdx.x;
    const int bid = blockIdx.x;
    const int dc    = (bid & 7) << 6;   // feature-chunk base (0..448)
    const int slice = bid >> 3;         // token-slice index  (0..127)
    const int i0    = slice << 7;       // first global token (slice never crosses batch)
    const int b     = i0 >> 10;
    const int hw0   = i0 & 1023;
    const float* xb = x + ((size_t)((b << 9) + dc) << 10) + hw0;   // x[b, dc, hw0]

    // Per-thread staging coordinates (same for every sub-tile).
    const int xf  = tid >> 2;           // feature row 0..63
    const int xc  = tid & 3;            // 16B chunk within 64B row
    const int mt  = tid >> 4;           // token 0..15
    const int mc4 = tid & 15;           // 16B chunk within 256B token row

    unsigned int xs_a[2], mu_a[2], lv_a[2];
    #pragma unroll
    for (int bi = 0; bi < 2; ++bi) {
        xs_a[bi] = (unsigned int)__cvta_generic_to_shared(xs[bi]);
        mu_a[bi] = (unsigned int)__cvta_generic_to_shared(mus[bi]);
        lv_a[bi] = (unsigned int)__cvta_generic_to_shared(lvs[bi]);
    }

    // Stage sub-tile s (tokens [16s, 16s+16)) into buffer bi. 3 cp.async/thread.
    auto stage = [&](int s, int bi) {
        const int toff = s << 4;
        cp16(xs_a[bi] + (unsigned int)xword(xf, xc) * 4u,
             xb + (size_t)xf * HW + toff + (xc << 2));
        const size_t off = (size_t)(i0 + toff + mt) * DD + dc + (mc4 << 2);
        const unsigned int so = (unsigned int)((mt << 6) + (mc4 << 2)) * 4u;
        cp16(mu_a[bi] + so, pmu + off);
        cp16(lv_a[bi] + so, plv + off);
        asm volatile("cp.async.commit_group;");
    };

    stage(0, 0);
    stage(1, 1);

    // ---- compute: thread owns feature f = tid&63, tokens [4*tseg, 4*tseg+4)
    //      within each 16-token sub-tile ----
    const int f    = tid & 63;
    const int tseg = tid >> 6;
    const int t0   = tseg << 2;
    const int xw   = xword(f, tseg);    // swizzled float4 word for this thread

    float sX = 0.f, sXX = 0.f, sS = 0.f, sT = 0.f, accP = 0.f;

    #pragma unroll
    for (int s = 0; s < 8; ++s) {
        const int bi = s & 1;
        if (s < 7) { asm volatile("cp.async.wait_group 1;" ::: "memory"); }
        else       { asm volatile("cp.async.wait_group 0;" ::: "memory"); }
        __syncthreads();

        const float4 xq = *reinterpret_cast<const float4*>(&xs[bi][xw]);
        const float xv[4] = {xq.x, xq.y, xq.z, xq.w};
        const float* mrow = mus[bi];
        const float* lrow = lvs[bi];
        #pragma unroll
        for (int e = 0; e < 4; ++e) {
            const int t = t0 + e;
            const float mu = mrow[(t << 6) + f];   // conflict-free
            const float lv = lrow[(t << 6) + f];
            const float iv = __expf(-lv);
            const float xx = xv[e] * xv[e];
            const float er = fmaf(xv[e] * mu, -2.0f, xx);   // x^2 - 2*x*mu
            accP = fmaf(er, iv, accP);
            sS  += iv;
            sT   = fmaf(mu, iv, sT);
            sX  += xv[e];
            sXX += xx;
        }
        if (s < 6) {                       // buffer bi will be refilled
            __syncthreads();               // everyone done with buffer bi
            stage(s + 2, bi);
        }
        // s == 6,7: no refill; epilogue's __syncthreads covers the hazard.
    }

    // ---- epilogue: reduce over the 4 token-segments per feature ----
    __syncthreads();
    red[(0 * 4 + tseg) * 64 + f] = sX;
    red[(1 * 4 + tseg) * 64 + f] = sXX;
    red[(2 * 4 + tseg) * 64 + f] = sS;
    red[(3 * 4 + tseg) * 64 + f] = sT;

    #pragma unroll
    for (int o = 16; o; o >>= 1) accP += __shfl_xor_sync(0xffffffffu, accP, o);
    if ((tid & 31) == 0) spc[tid >> 5] = accP;
    __syncthreads();

    {
        const int a  = tid >> 6;      // accumulator 0..3
        const int ff = tid & 63;
        const float s = red[(a * 4 + 0) * 64 + ff] + red[(a * 4 + 1) * 64 + ff]
                      + red[(a * 4 + 2) * 64 + ff] + red[(a * 4 + 3) * 64 + ff];
        atomicAdd(&gAcc[a * DD + dc + ff], s);   // REDG, 128 adds/address
    }
    if (tid == 0) {
        float s = 0.f;
        #pragma unroll
        for (int ww = 0; ww < 8; ++ww) s += spc[ww];
        gP[bid] = s;
    }

    // ---- last-block ticket finalize ----
    __syncthreads();            // all this block's atomics + gP store issued
    __threadfence();            // ... and globally visible
    if (tid == 0) {
        unsigned v = atomicAdd(&gTicket, 1u);
        amLast = (v == 1023u);
    }
    __syncthreads();
    if (!amLast) return;

    // Last block: all 1024 blocks' atomics and fenced stores are L2-visible.
    // Combine 12 KB in double; thread handles features tid and tid+256.
    double term = 0.0, psum = 0.0;
    #pragma unroll
    for (int k = 0; k < 2; ++k) {
        const int d = tid + (k << 8);
        const double X  = (double)__ldcg(&gAcc[0 * DD + d]);
        const double XX = (double)__ldcg(&gAcc[1 * DD + d]);
        const double S  = (double)__ldcg(&gAcc[2 * DD + d]);
        const double T  = (double)__ldcg(&gAcc[3 * DD + d]);
        term += XX * S - 2.0 * X * T;
        // re-zero for the next graph replay
        gAcc[0 * DD + d] = 0.f;
        gAcc[1 * DD + d] = 0.f;
        gAcc[2 * DD + d] = 0.f;
        gAcc[3 * DD + d] = 0.f;
    }
    #pragma unroll
    for (int k = 0; k < 4; ++k) psum += (double)__ldcg(&gP[tid + (k << 8)]);

    // block reduce (8 warps)
    #pragma unroll
    for (int o = 16; o; o >>= 1) {
        term += __shfl_xor_sync(0xffffffffu, term, o);
        psum += __shfl_xor_sync(0xffffffffu, psum, o);
    }
    __shared__ double sdw[8], spw[8];
    if ((tid & 31) == 0) { sdw[tid >> 5] = term; spw[tid >> 5] = psum; }
    __syncthreads();
    if (tid == 0) {
        double td = 0.0, tp = 0.0;
        #pragma unroll
        for (int wz = 0; wz < 8; ++wz) { td += sdw[wz]; tp += spw[wz]; }
        const double N = (double)NTOK;
        out[0] = (float)((-0.5 * tp + 0.5 * td / N) / N);
        gTicket = 0u;               // restore invariant for next replay
    }
}

extern "C" void kernel_launch(void* const* d_in, const int* in_sizes, int n_in,
                              void* d_out, int out_size)
{
    const float* x   = (const float*)d_in[0];
    const float* pmu = (const float*)d_in[1];
    const float* plv = (const float*)d_in[2];
    float* out = (float*)d_out;

    club_main_kernel<<<1024, 256>>>(x, pmu, plv, out);
}

// round 16
// speedup vs baseline: 1.1096x; 1.1096x over previous
#include <cuda_runtime.h>
#include <cuda_bf16.h>
#include <cstdint>

// CLUB loss, single-pass formulation.
//   result = ( -0.5*P + 0.5/N * sum_d [ X2_d*S_d - 2*X_d*T_d ] ) / N
// with  P    = sum_{i,d} (x^2 - 2*x*mu) * exp(-lv)
//       X_d  = sum_i x,   X2_d = sum_i x^2
//       S_d  = sum_i exp(-lv),   T_d = sum_i mu*exp(-lv)
// (The mu^2 terms cancel between positive and negative.)
//
// Shapes: x (16,512,32,32) f32, p_mu (16384,512) f32, p_logvar (16384,512) f32.
//
// Single fused kernel: pipelined cp.async streaming (R13 main, frozen) +
// atomicAdd per-d combine + last-block ticket finalize.
// __launch_bounds__(256, 8) pins regs <= 32 so the streaming loop keeps
// 8 blocks/SM (the R15 fusion regressed purely via regs 32->35 -> occ drop).

#define DD   512
#define HW   1024
#define NTOK 16384

// Per-launch accumulators. Zero at load; the last block re-zeroes after
// consuming, so the zero-at-entry invariant holds across graph replays.
__device__ float        gAcc[4 * DD];   // [a][d] atomic accumulation targets
__device__ float        gP[1024];       // per-block scalar partials (overwritten)
__device__ unsigned int gTicket;        // reset to 0 by last block each launch

__device__ __forceinline__ void cp16(unsigned int dst, const float* src) {
    asm volatile("cp.async.cg.shared.global [%0], [%1], 16;" :: "r"(dst), "l"(src));
}

// x tile: [feature][16 tokens], pitch 16 floats, XOR chunk swizzle
// c' = c ^ ((f>>1)&3) -> conflict-free LDS.128 on store and load sides.
__device__ __forceinline__ int xword(int f, int c) {
    return (f << 4) + ((c ^ ((f >> 1) & 3)) << 2);
}

// Grid: 1024 blocks = 8 feature-chunks (64 each) x 128 token-slices (128 each).
__global__ __launch_bounds__(256, 8) void club_main_kernel(
    const float* __restrict__ x,
    const float* __restrict__ pmu,
    const float* __restrict__ plv,
    float* __restrict__ out)
{
    __shared__ float xs[2][64 * 16];    // 2 x 4 KB
    __shared__ float mus[2][16 * 64];   // 2 x 4 KB
    __shared__ float lvs[2][16 * 64];   // 2 x 4 KB
    __shared__ float red[4 * 4 * 64];   // [acc][tseg][feature]
    __shared__ float spc[8];
    __shared__ bool  amLast;

    const int tid = threadIdx.x;
    const int bid = blockIdx.x;
    const int dc    = (bid & 7) << 6;   // feature-chunk base (0..448)
    const int slice = bid >> 3;         // token-slice index  (0..127)
    const int i0    = slice << 7;       // first global token (slice never crosses batch)
    const int b     = i0 >> 10;
    const int hw0   = i0 & 1023;
    const float* xb = x + ((size_t)((b << 9) + dc) << 10) + hw0;   // x[b, dc, hw0]

    // Per-thread staging coordinates (same for every sub-tile).
    const int xf  = tid >> 2;           // feature row 0..63
    const int xc  = tid & 3;            // 16B chunk within 64B row
    const int mt  = tid >> 4;           // token 0..15
    const int mc4 = tid & 15;           // 16B chunk within 256B token row

    unsigned int xs_a[2], mu_a[2], lv_a[2];
    #pragma unroll
    for (int bi = 0; bi < 2; ++bi) {
        xs_a[bi] = (unsigned int)__cvta_generic_to_shared(xs[bi]);
        mu_a[bi] = (unsigned int)__cvta_generic_to_shared(mus[bi]);
        lv_a[bi] = (unsigned int)__cvta_generic_to_shared(lvs[bi]);
    }

    // Stage sub-tile s (tokens [16s, 16s+16)) into buffer bi. 3 cp.async/thread.
    auto stage = [&](int s, int bi) {
        const int toff = s << 4;
        cp16(xs_a[bi] + (unsigned int)xword(xf, xc) * 4u,
             xb + (size_t)xf * HW + toff + (xc << 2));
        const size_t off = (size_t)(i0 + toff + mt) * DD + dc + (mc4 << 2);
        const unsigned int so = (unsigned int)((mt << 6) + (mc4 << 2)) * 4u;
        cp16(mu_a[bi] + so, pmu + off);
        cp16(lv_a[bi] + so, plv + off);
        asm volatile("cp.async.commit_group;");
    };

    stage(0, 0);
    stage(1, 1);

    // ---- compute: thread owns feature f = tid&63, tokens [4*tseg, 4*tseg+4)
    //      within each 16-token sub-tile ----
    const int f    = tid & 63;
    const int tseg = tid >> 6;
    const int t0   = tseg << 2;
    const int xw   = xword(f, tseg);    // swizzled float4 word for this thread

    float sX = 0.f, sXX = 0.f, sS = 0.f, sT = 0.f, accP = 0.f;

    #pragma unroll
    for (int s = 0; s < 8; ++s) {
        const int bi = s & 1;
        if (s < 7) { asm volatile("cp.async.wait_group 1;" ::: "memory"); }
        else       { asm volatile("cp.async.wait_group 0;" ::: "memory"); }
        __syncthreads();

        const float4 xq = *reinterpret_cast<const float4*>(&xs[bi][xw]);
        const float xv[4] = {xq.x, xq.y, xq.z, xq.w};
        const float* mrow = mus[bi];
        const float* lrow = lvs[bi];
        #pragma unroll
        for (int e = 0; e < 4; ++e) {
            const int t = t0 + e;
            const float mu = mrow[(t << 6) + f];   // conflict-free
            const float lv = lrow[(t << 6) + f];
            const float iv = __expf(-lv);
            const float xx = xv[e] * xv[e];
            const float er = fmaf(xv[e] * mu, -2.0f, xx);   // x^2 - 2*x*mu
            accP = fmaf(er, iv, accP);
            sS  += iv;
            sT   = fmaf(mu, iv, sT);
            sX  += xv[e];
            sXX += xx;
        }
        if (s < 6) {                       // buffer bi will be refilled
            __syncthreads();               // everyone done with buffer bi
            stage(s + 2, bi);
        }
        // s == 6,7: no refill; epilogue's __syncthreads covers the hazard.
    }

    // ---- epilogue: reduce over the 4 token-segments per feature ----
    __syncthreads();
    red[(0 * 4 + tseg) * 64 + f] = sX;
    red[(1 * 4 + tseg) * 64 + f] = sXX;
    red[(2 * 4 + tseg) * 64 + f] = sS;
    red[(3 * 4 + tseg) * 64 + f] = sT;

    #pragma unroll
    for (int o = 16; o; o >>= 1) accP += __shfl_xor_sync(0xffffffffu, accP, o);
    if ((tid & 31) == 0) spc[tid >> 5] = accP;
    __syncthreads();

    {
        const int a  = tid >> 6;      // accumulator 0..3
        const int ff = tid & 63;
        const float s = red[(a * 4 + 0) * 64 + ff] + red[(a * 4 + 1) * 64 + ff]
                      + red[(a * 4 + 2) * 64 + ff] + red[(a * 4 + 3) * 64 + ff];
        atomicAdd(&gAcc[a * DD + dc + ff], s);   // REDG, 128 adds/address
    }
    if (tid == 0) {
        float s = 0.f;
        #pragma unroll
        for (int ww = 0; ww < 8; ++ww) s += spc[ww];
        gP[bid] = s;
    }

    // ---- last-block ticket finalize ----
    __syncthreads();            // all this block's atomics + gP store issued
    __threadfence();            // ... and globally visible
    if (tid == 0) {
        unsigned v = atomicAdd(&gTicket, 1u);
        amLast = (v == 1023u);
    }
    __syncthreads();
    if (!amLast) return;

    // Last block: all 1024 blocks' atomics and fenced stores are L2-visible.
    // Combine 12 KB in double; thread handles features tid and tid+256.
    // (Runs once per launch; any register spills here are irrelevant.)
    double term = 0.0, psum = 0.0;
    #pragma unroll
    for (int k = 0; k < 2; ++k) {
        const int d = tid + (k << 8);
        const double X  = (double)__ldcg(&gAcc[0 * DD + d]);
        const double XX = (double)__ldcg(&gAcc[1 * DD + d]);
        const double S  = (double)__ldcg(&gAcc[2 * DD + d]);
        const double T  = (double)__ldcg(&gAcc[3 * DD + d]);
        term += XX * S - 2.0 * X * T;
        // re-zero for the next graph replay
        gAcc[0 * DD + d] = 0.f;
        gAcc[1 * DD + d] = 0.f;
        gAcc[2 * DD + d] = 0.f;
        gAcc[3 * DD + d] = 0.f;
    }
    #pragma unroll
    for (int k = 0; k < 4; ++k) psum += (double)__ldcg(&gP[tid + (k << 8)]);

    // block reduce (8 warps)
    #pragma unroll
    for (int o = 16; o; o >>= 1) {
        term += __shfl_xor_sync(0xffffffffu, term, o);
        psum += __shfl_xor_sync(0xffffffffu, psum, o);
    }
    __shared__ double sdw[8], spw[8];
    if ((tid & 31) == 0) { sdw[tid >> 5] = term; spw[tid >> 5] = psum; }
    __syncthreads();
    if (tid == 0) {
        double td = 0.0, tp = 0.0;
        #pragma unroll
        for (int wz = 0; wz < 8; ++wz) { td += sdw[wz]; tp += spw[wz]; }
        const double N = (double)NTOK;
        out[0] = (float)((-0.5 * tp + 0.5 * td / N) / N);
        gTicket = 0u;               // restore invariant for next replay
    }
}

extern "C" void kernel_launch(void* const* d_in, const int* in_sizes, int n_in,
                              void* d_out, int out_size)
{
    const float* x   = (const float*)d_in[0];
    const float* pmu = (const float*)d_in[1];
    const float* plv = (const float*)d_in[2];
    float* out = (float*)d_out;

    club_main_kernel<<<1024, 256>>>(x, pmu, plv, out);
}